// round 3
// baseline (speedup 1.0000x reference)
#include <cuda_runtime.h>
#include <math.h>

#define BB    16
#define CINN  64
#define COUTT 64
#define HH    256
#define WW    256
#define M1N   32
#define M2N   32
#define KXN   64   // 2*M1 (rows 0..31 and 224..255)

typedef unsigned long long u64;

__device__ __forceinline__ u64 pk2(float x, float y) {
    u64 r; asm("mov.b64 %0,{%1,%2};" : "=l"(r) : "f"(x), "f"(y)); return r;
}
__device__ __forceinline__ float2 up2(u64 v) {
    float2 r; asm("mov.b64 {%0,%1},%2;" : "=f"(r.x), "=f"(r.y) : "l"(v)); return r;
}
// packed (d.x += a.x*b.x ; d.y += a.y*b.y) in ONE fma-pipe slot
__device__ __forceinline__ void fma2(u64& d, u64 a, u64 b) {
    asm("fma.rn.f32x2 %0,%1,%2,%0;" : "+l"(d) : "l"(a), "l"(b));
}
__device__ __forceinline__ u64 lds2(const float2* p) {
    return *reinterpret_cast<const u64*>(p);
}

// Scratch: spectral intermediates, ~16.8MB each.
__device__ float2 g_Xf  [BB * CINN  * KXN * M2N];  // [b][i][kxi][ky]
__device__ float2 g_T   [BB * COUTT * KXN * M2N];  // [b][c][kxi][ky]
__device__ float2 g_OutF[BB * COUTT * KXN * M2N];  // [b][o][kxi][ky]

// ---------------------------------------------------------------------------
// K12: partial rfft2 to the 64x32 mode corner.
// tw  = e^{-2pi i k/256} = (cos, -sin);  twj = (-tw.y, tw.x) = (sin, cos)
// 16-row tiles; stage1 processes 2 rows/thread sharing each twiddle load.
// ---------------------------------------------------------------------------
__global__ void __launch_bounds__(256, 2) k12_forward(const float* __restrict__ x) {
    __shared__ float  sx[16][256];     // 16KB
    __shared__ float2 eo[16][128];     // 16KB  (even,odd) pairs, w=1..127
    __shared__ float2 sxw[16][32];     // 4KB   per-row W-DFT result
    __shared__ float2 tw[256];         // 2KB
    __shared__ float2 twj[256];        // 2KB

    const int tid = threadIdx.x;
    const int i = blockIdx.x, b = blockIdx.y;
    {
        float s, c;
        sincospif((float)tid / 128.0f, &s, &c);
        tw[tid]  = make_float2(c, -s);
        twj[tid] = make_float2(s,  c);   // (-(-s), c)
    }
    const int ky  = tid & 31;
    const int pr  = tid >> 5;          // row-pair index for stage1 (rows 2pr,2pr+1)
    const int kx0 = (tid >> 5) << 3;   // 8 kxi per thread for stage2
    const int kxbase = (kx0 < 32) ? kx0 : (192 + kx0);

    u64 acc[8];
#pragma unroll
    for (int j = 0; j < 8; j++) acc[j] = 0ull;

    const float* xrow = x + (size_t)(b * CINN + i) * HH * WW;

    for (int hb = 0; hb < HH; hb += 16) {
        __syncthreads();   // prev stage-2 done reading sxw
#pragma unroll
        for (int r = 0; r < 16; r++)
            sx[r][tid] = xrow[(hb + r) * WW + tid];
        __syncthreads();
        // even/odd prep: hl = tid>>4 (16 rows), w = (tid&15)+1 step 16
        {
            int hl = tid >> 4;
#pragma unroll
            for (int w = (tid & 15) + 1; w < 128; w += 16) {
                float a = sx[hl][w], c2 = sx[hl][256 - w];
                eo[hl][w] = make_float2(a + c2, a - c2);
            }
        }
        __syncthreads();
        // stage 1: W-axis partial DFT, 2 rows per thread share each twiddle
        {
            const int r0 = 2 * pr, r1 = r0 + 1;
            float sgn = (ky & 1) ? -1.f : 1.f;
            u64 a0 = pk2(fmaf(sgn, sx[r0][128], sx[r0][0]), 0.f);
            u64 a1 = pk2(fmaf(sgn, sx[r1][128], sx[r1][0]), 0.f);
            int idx = ky;
#pragma unroll 127
            for (int w = 1; w < 128; w++) {
                u64 t  = lds2(&tw[idx]);
                fma2(a0, lds2(&eo[r0][w]), t);   // re += e.x*cos ; im += e.y*(-sin)
                fma2(a1, lds2(&eo[r1][w]), t);
                idx = (idx + ky) & 255;
            }
            sxw[r0][ky] = up2(a0);
            sxw[r1][ky] = up2(a1);
        }
        __syncthreads();
        // stage 2: H-axis partial DFT, packed complex MAC (2 FFMA2/mode)
#pragma unroll
        for (int hl = 0; hl < 16; hl++) {
            float2 v = sxw[hl][ky];
            u64 vxx = pk2(v.x, v.x);
            u64 vyy = pk2(v.y, v.y);
            int h = hb + hl;
            int idx  = (kxbase * h) & 255;
            int step = h & 255;
#pragma unroll
            for (int j = 0; j < 8; j++) {
                fma2(acc[j], vxx, lds2(&tw[idx]));   // broadcast LDS
                fma2(acc[j], vyy, lds2(&twj[idx]));  // broadcast LDS
                idx = (idx + step) & 255;
            }
        }
    }
    const float sc = 1.0f / 256.0f;   // ortho forward scaling
#pragma unroll
    for (int j = 0; j < 8; j++) {
        float2 a = up2(acc[j]);
        g_Xf[((b * CINN + i) * KXN + kx0 + j) * M2N + ky] =
            make_float2(a.x * sc, a.y * sc);
    }
}

// ---------------------------------------------------------------------------
// K3a: t[b,c,kxi,ky] = sum_i Xf[b,i,kxi,ky] * w{1|2}[i,c,m]
// ---------------------------------------------------------------------------
__global__ void __launch_bounds__(256, 2) k3a_mixx(const float* __restrict__ wx1,
                                                   const float* __restrict__ wx2) {
    __shared__ float2 sX [CINN][M2N];    // 16KB
    __shared__ float2 sW [CINN][COUTT];  // 32KB
    __shared__ float2 sWj[CINN][COUTT];  // 32KB rotated weights
    const int tid = threadIdx.x;
    const int kxi = blockIdx.x, b = blockIdx.y;
    const int m = (kxi < 32) ? kxi : (kxi - 32);
    const float2* wsrc = (const float2*)((kxi < 32) ? wx1 : wx2);

    for (int idx = tid; idx < CINN * M2N; idx += 256) {
        int i = idx >> 5, k = idx & 31;
        sX[i][k] = g_Xf[((b * CINN + i) * KXN + kxi) * M2N + k];
    }
    for (int idx = tid; idx < CINN * COUTT; idx += 256) {
        int i = idx >> 6, c = idx & 63;
        float2 w = wsrc[(i * COUTT + c) * M1N + m];
        sW [i][c] = w;
        sWj[i][c] = make_float2(-w.y, w.x);
    }
    __syncthreads();

    const int ky = tid & 31;
    const int cb = (tid >> 5) << 3;
    u64 acc[8];
#pragma unroll
    for (int j = 0; j < 8; j++) acc[j] = 0ull;
    for (int i = 0; i < CINN; i++) {
        float2 xv = sX[i][ky];
        u64 vxx = pk2(xv.x, xv.x), vyy = pk2(xv.y, xv.y);
#pragma unroll
        for (int j = 0; j < 8; j++) {
            fma2(acc[j], vxx, lds2(&sW [i][cb + j]));  // broadcast
            fma2(acc[j], vyy, lds2(&sWj[i][cb + j]));  // broadcast
        }
    }
#pragma unroll
    for (int j = 0; j < 8; j++)
        g_T[((b * COUTT + cb + j) * KXN + kxi) * M2N + ky] = up2(acc[j]);
}

// ---------------------------------------------------------------------------
// K3b: OutF[b,o,kxi,ky] = sum_c t[b,c,kxi,ky] * wy[c,o,ky]
// ---------------------------------------------------------------------------
__global__ void __launch_bounds__(256, 2) k3b_mixy(const float* __restrict__ wy) {
    __shared__ float2 sT  [32][KXN];     // 16KB
    __shared__ float2 sWy [32][COUTT];   // 16KB
    __shared__ float2 sWyj[32][COUTT];   // 16KB
    const int tid = threadIdx.x;
    const int ky = blockIdx.x, b = blockIdx.y;
    const int kxi = tid & 63;
    const int ob = (tid >> 6) << 4;
    const float2* wyp = (const float2*)wy;

    u64 acc[16];
#pragma unroll
    for (int j = 0; j < 16; j++) acc[j] = 0ull;

    for (int cb = 0; cb < COUTT; cb += 32) {
        __syncthreads();
        for (int idx = tid; idx < 32 * KXN; idx += 256) {
            int cl = idx >> 6, kk = idx & 63;
            sT[cl][kk] = g_T[((b * COUTT + cb + cl) * KXN + kk) * M2N + ky];
        }
        for (int idx = tid; idx < 32 * COUTT; idx += 256) {
            int cl = idx >> 6, o = idx & 63;
            float2 w = wyp[((cb + cl) * COUTT + o) * M2N + ky];
            sWy [cl][o] = w;
            sWyj[cl][o] = make_float2(-w.y, w.x);
        }
        __syncthreads();
        for (int cl = 0; cl < 32; cl++) {
            float2 tv = sT[cl][kxi];
            u64 vxx = pk2(tv.x, tv.x), vyy = pk2(tv.y, tv.y);
#pragma unroll
            for (int j = 0; j < 16; j++) {
                fma2(acc[j], vxx, lds2(&sWy [cl][ob + j]));  // broadcast
                fma2(acc[j], vyy, lds2(&sWyj[cl][ob + j]));  // broadcast
            }
        }
    }
#pragma unroll
    for (int j = 0; j < 16; j++)
        g_OutF[((b * COUTT + ob + j) * KXN + kxi) * M2N + ky] = up2(acc[j]);
}

// ---------------------------------------------------------------------------
// K45: fused inverse. tw = e^{+2pi i k/256} = (cos, sin)
// phase A: Z[h,ky] = sum_kxi OutF[kxi,ky] e^{+2pi i kx h/256}  (t hoisted over 2 ky)
// phase B: outer-ky / inner-8-rows; z LDS is a warp broadcast, 1 FFMA2 per pair.
// ---------------------------------------------------------------------------
__global__ void __launch_bounds__(256, 2) k45_inverse(float* __restrict__ out) {
    __shared__ float2 sF[KXN][M2N];  // 16KB
    __shared__ float2 tw[256];       // 2KB
    __shared__ float2 sZ[16][M2N];   // 4KB

    const int tid = threadIdx.x;
    const int hb = blockIdx.x;       // 0..15 (tiles of 16 rows)
    const int o = blockIdx.y, b = blockIdx.z;
    {
        float s, c;
        sincospif((float)tid / 128.0f, &s, &c);
        tw[tid] = make_float2(c, s);
    }
    const float2* src = g_OutF + (size_t)(b * COUTT + o) * KXN * M2N;
    for (int idx = tid; idx < KXN * M2N; idx += 256)
        sF[idx >> 5][idx & 31] = src[idx];
    __syncthreads();

    // phase A: each thread computes 2 ky values sharing each twiddle
    {
        const int hl = tid >> 4;
        const int kyp = tid & 15;
        const int h = hb * 16 + hl;
        const int step = h & 255;
        float re0 = 0.f, im0 = 0.f, re1 = 0.f, im1 = 0.f;
        int idx = 0;
#pragma unroll 16
        for (int kxi = 0; kxi < 32; kxi++) {
            float2 t = tw[idx];
            float2 v0 = sF[kxi][kyp];
            float2 v1 = sF[kxi][kyp + 16];
            re0 = fmaf(v0.x, t.x, fmaf(-v0.y, t.y, re0));
            im0 = fmaf(v0.x, t.y, fmaf( v0.y, t.x, im0));
            re1 = fmaf(v1.x, t.x, fmaf(-v1.y, t.y, re1));
            im1 = fmaf(v1.x, t.y, fmaf( v1.y, t.x, im1));
            idx = (idx + step) & 255;
        }
        idx = (224 * h) & 255;   // kx = 224 at kxi = 32
#pragma unroll 16
        for (int kxi = 32; kxi < 64; kxi++) {
            float2 t = tw[idx];
            float2 v0 = sF[kxi][kyp];
            float2 v1 = sF[kxi][kyp + 16];
            re0 = fmaf(v0.x, t.x, fmaf(-v0.y, t.y, re0));
            im0 = fmaf(v0.x, t.y, fmaf( v0.y, t.x, im0));
            re1 = fmaf(v1.x, t.x, fmaf(-v1.y, t.y, re1));
            im1 = fmaf(v1.x, t.y, fmaf( v1.y, t.x, im1));
            idx = (idx + step) & 255;
        }
        sZ[hl][kyp]      = make_float2(re0, im0);
        sZ[hl][kyp + 16] = make_float2(re1, im1);
    }
    __syncthreads();

    // phase B: 8 rows per thread; outer ky, inner rows (twiddle amortized x8)
    {
        const int p  = tid & 127;
        const int hh = tid >> 7;
        const int r0 = hh * 8;
        const float sc = 1.0f / 256.0f;
        float* orow = out + ((size_t)(b * COUTT + o) * HH + hb * 16 + r0) * WW;

        float zr0[8];
        u64 acc[8];
#pragma unroll
        for (int r = 0; r < 8; r++) { zr0[r] = sZ[r0 + r][0].x; acc[r] = 0ull; }

        int idx = p;
#pragma unroll 31
        for (int kk = 1; kk < 32; kk++) {
            u64 t = lds2(&tw[idx]);          // per-lane gather, 1 per 8 rows
            idx = (idx + p) & 255;
#pragma unroll
            for (int r = 0; r < 8; r++)
                fma2(acc[r], lds2(&sZ[r0 + r][kk]), t);   // broadcast LDS
        }

#pragma unroll
        for (int r = 0; r < 8; r++) {
            float2 a = up2(acc[r]);          // (sum Re*cos, sum Im*sin)
            orow[r * WW + p] = (zr0[r] + 2.f * (a.x - a.y)) * sc;
            if (p > 0) {
                orow[r * WW + (256 - p)] = (zr0[r] + 2.f * (a.x + a.y)) * sc;
            } else {
                // w = 128 column: cos = (-1)^ky, sin = 0
                float a128 = 0.f;
#pragma unroll 31
                for (int kk = 1; kk < 32; kk++) {
                    float zr = sZ[r0 + r][kk].x;
                    a128 += (kk & 1) ? -zr : zr;
                }
                orow[r * WW + 128] = (zr0[r] + 2.f * a128) * sc;
            }
        }
    }
}

extern "C" void kernel_launch(void* const* d_in, const int* in_sizes, int n_in,
                              void* d_out, int out_size) {
    const float* x   = (const float*)d_in[0];
    const float* wx1 = (const float*)d_in[1];
    const float* wx2 = (const float*)d_in[2];
    const float* wy  = (const float*)d_in[3];
    float* out = (float*)d_out;

    k12_forward<<<dim3(CINN, BB), 256>>>(x);
    k3a_mixx  <<<dim3(KXN, BB), 256>>>(wx1, wx2);
    k3b_mixy  <<<dim3(M2N, BB), 256>>>(wy);
    k45_inverse<<<dim3(16, COUTT, BB), 256>>>(out);
}

// round 5
// speedup vs baseline: 2.6376x; 2.6376x over previous
#include <cuda_runtime.h>
#include <math.h>

#define BB    16
#define CINN  64
#define COUTT 64
#define HH    256
#define WW    256
#define M1N   32
#define M2N   32
#define KXN   64   // rows 0..31 and 224..255

// ---------------- scratch ----------------
__device__ float  g_Y1[BB * CINN * HH * 64];           // [b,i,h][2ky+t]  67MB
__device__ float2 g_Xf  [BB * CINN  * KXN * M2N];      // [b][i][kxi][ky] 16.8MB
__device__ float2 g_T   [BB * COUTT * KXN * M2N];      // [b][c][kxi][ky]
__device__ float2 g_OutF[BB * COUTT * KXN * M2N];      // [b][o][kxi][ky]
__device__ float  g_Z [BB * COUTT * HH * 64];          // [b,o][h][2ky+t] 67MB
// stationary matrices
__device__ float g_B1[256 * 64];    // [w][2ky+t]          fwd W-DFT, scale 1/16
__device__ float g_A2[128 * 512];   // [2kxi+t][2h+s]      fwd H-DFT, scale 1/16
__device__ float g_A5[512 * 128];   // [2h+t][2kxi+s]      inv H-DFT
__device__ float g_C6[64 * 256];    // [2ky+t][w]          inv W (irfft), scale 1/256

// ---------------- tf32 mma helpers ----------------
__device__ __forceinline__ unsigned tf32of(float x) {
    unsigned r; asm("cvt.rna.tf32.f32 %0,%1;" : "=r"(r) : "f"(x)); return r;
}
__device__ __forceinline__ void split2(float x, unsigned& h, unsigned& l) {
    h = tf32of(x);
    l = tf32of(x - __uint_as_float(h));
}
__device__ __forceinline__ void mma1(float* c, const unsigned* a, const unsigned* b) {
    asm volatile(
        "mma.sync.aligned.m16n8k8.row.col.f32.tf32.tf32.f32 "
        "{%0,%1,%2,%3},{%4,%5,%6,%7},{%8,%9},{%0,%1,%2,%3};"
        : "+f"(c[0]), "+f"(c[1]), "+f"(c[2]), "+f"(c[3])
        : "r"(a[0]), "r"(a[1]), "r"(a[2]), "r"(a[3]), "r"(b[0]), "r"(b[1]));
}
__device__ __forceinline__ void mma3(float* c, const unsigned* ah, const unsigned* al,
                                     const unsigned* bh, const unsigned* bl) {
    mma1(c, ah, bh);
    mma1(c, al, bh);
    mma1(c, ah, bl);
}

// ---------------- fill kernels ----------------
__global__ void __launch_bounds__(256) fill_B1() {
    int idx = blockIdx.x * 256 + threadIdx.x;           // 16384
    int w = idx >> 6, n = idx & 63, ky = n >> 1, t = n & 1;
    float s, c; sincospif((float)((w * ky) & 255) / 128.0f, &s, &c);
    g_B1[idx] = (t == 0 ? c : -s) * (1.0f / 16.0f);
}
__global__ void __launch_bounds__(256) fill_A2() {
    int idx = blockIdx.x * 256 + threadIdx.x;           // 65536
    int row = idx >> 9, col = idx & 511;
    int kxi = row >> 1, t = row & 1, h = col >> 1, s2 = col & 1;
    int kx = (kxi < 32) ? kxi : (192 + kxi);
    float s, c; sincospif((float)((kx * h) & 255) / 128.0f, &s, &c);
    // e^{-i theta}: re += c*u + s*v ; im += -s*u + c*v
    float v = (t == 0) ? ((s2 == 0) ? c : s) : ((s2 == 0) ? -s : c);
    g_A2[idx] = v * (1.0f / 16.0f);
}
__global__ void __launch_bounds__(256) fill_A5() {
    int idx = blockIdx.x * 256 + threadIdx.x;           // 65536
    int row = idx >> 7, col = idx & 127;
    int h = row >> 1, t = row & 1, kxi = col >> 1, s2 = col & 1;
    int kx = (kxi < 32) ? kxi : (192 + kxi);
    float s, c; sincospif((float)((kx * h) & 255) / 128.0f, &s, &c);
    // e^{+i theta}: re = c*u - s*v ; im = s*u + c*v
    g_A5[idx] = (t == 0) ? ((s2 == 0) ? c : -s) : ((s2 == 0) ? s : c);
}
__global__ void __launch_bounds__(256) fill_C6() {
    int idx = blockIdx.x * 256 + threadIdx.x;           // 16384
    int k = idx >> 8, w = idx & 255;
    int ky = k >> 1, t = k & 1;
    float s, c; sincospif((float)((ky * w) & 255) / 128.0f, &s, &c);
    float base = ((ky == 0) ? 1.0f : 2.0f) * (1.0f / 256.0f);
    g_C6[idx] = (t == 0) ? base * c : ((ky == 0) ? 0.0f : -base * s);
}

// ---------------- S1: Y1[r, 2ky+t] = x[r, :] @ B1  (M=262144, K=256, N=64) ----------------
__global__ void __launch_bounds__(256) s1_wdft(const float* __restrict__ x) {
    __shared__ float sA[128][33];
    __shared__ float sB[32][65];
    const int tid = threadIdx.x, warp = tid >> 5, lane = tid & 31;
    const int g = lane >> 2, tg = lane & 3;
    const int r0 = blockIdx.x * 128;

    float c[8][4];
#pragma unroll
    for (int i = 0; i < 8; i++)
#pragma unroll
        for (int j = 0; j < 4; j++) c[i][j] = 0.f;

    for (int kc = 0; kc < 8; kc++) {
        __syncthreads();
        for (int i = tid; i < 128 * 32; i += 256) {
            int row = i >> 5, col = i & 31;
            sA[row][col] = x[(size_t)(r0 + row) * 256 + kc * 32 + col];
        }
        for (int i = tid; i < 32 * 64; i += 256) {
            int k = i >> 6, n = i & 63;
            sB[k][n] = g_B1[(kc * 32 + k) * 64 + n];
        }
        __syncthreads();
#pragma unroll
        for (int ks = 0; ks < 4; ks++) {
            unsigned ah[4], al[4];
            split2(sA[warp * 16 + g    ][ks * 8 + tg    ], ah[0], al[0]);
            split2(sA[warp * 16 + g + 8][ks * 8 + tg    ], ah[1], al[1]);
            split2(sA[warp * 16 + g    ][ks * 8 + tg + 4], ah[2], al[2]);
            split2(sA[warp * 16 + g + 8][ks * 8 + tg + 4], ah[3], al[3]);
#pragma unroll
            for (int nt = 0; nt < 8; nt++) {
                unsigned bh[2], bl[2];
                split2(sB[ks * 8 + tg    ][nt * 8 + g], bh[0], bl[0]);
                split2(sB[ks * 8 + tg + 4][nt * 8 + g], bh[1], bl[1]);
                mma3(c[nt], ah, al, bh, bl);
            }
        }
    }
#pragma unroll
    for (int nt = 0; nt < 8; nt++) {
        int row = r0 + warp * 16 + g;
        int col = nt * 8 + 2 * tg;
        *(float2*)&g_Y1[(size_t)row * 64 + col]       = make_float2(c[nt][0], c[nt][1]);
        *(float2*)&g_Y1[(size_t)(row + 8) * 64 + col] = make_float2(c[nt][2], c[nt][3]);
    }
}

// ---------------- S2: Xf = A2 @ Y1slab  (per (b,i): M=128, K=512, N=32) ----------------
__global__ void __launch_bounds__(256) s2_hdft() {
    __shared__ float sA[128][33];
    __shared__ float sY[16][66];
    const int tid = threadIdx.x, warp = tid >> 5, lane = tid & 31;
    const int g = lane >> 2, tg = lane & 3;
    const int bi = blockIdx.x;

    float c[4][4];
#pragma unroll
    for (int i = 0; i < 4; i++)
#pragma unroll
        for (int j = 0; j < 4; j++) c[i][j] = 0.f;

    for (int kc = 0; kc < 16; kc++) {
        __syncthreads();
        for (int i = tid; i < 128 * 32; i += 256) {
            int row = i >> 5, col = i & 31;
            sA[row][col] = g_A2[row * 512 + kc * 32 + col];
        }
        for (int i = tid; i < 16 * 64; i += 256) {
            int h = i >> 6, cc = i & 63;
            sY[h][cc] = g_Y1[((size_t)bi * 256 + kc * 16 + h) * 64 + cc];
        }
        __syncthreads();
#pragma unroll
        for (int ks = 0; ks < 4; ks++) {
            unsigned ah[4], al[4];
            split2(sA[warp * 16 + g    ][ks * 8 + tg    ], ah[0], al[0]);
            split2(sA[warp * 16 + g + 8][ks * 8 + tg    ], ah[1], al[1]);
            split2(sA[warp * 16 + g    ][ks * 8 + tg + 4], ah[2], al[2]);
            split2(sA[warp * 16 + g + 8][ks * 8 + tg + 4], ah[3], al[3]);
            int k0 = ks * 8 + tg, k1 = k0 + 4;
#pragma unroll
            for (int nt = 0; nt < 4; nt++) {
                unsigned bh[2], bl[2];
                int n = nt * 8 + g;
                split2(sY[k0 >> 1][2 * n + (k0 & 1)], bh[0], bl[0]);
                split2(sY[k1 >> 1][2 * n + (k1 & 1)], bh[1], bl[1]);
                mma3(c[nt], ah, al, bh, bl);
            }
        }
    }
    float* xf = (float*)g_Xf + (size_t)bi * 4096;
#pragma unroll
    for (int nt = 0; nt < 4; nt++) {
        int m0 = warp * 16 + g, m1 = m0 + 8;
        int n0 = nt * 8 + 2 * tg, n1 = n0 + 1;
        xf[(m0 >> 1) * 64 + 2 * n0 + (m0 & 1)] = c[nt][0];
        xf[(m0 >> 1) * 64 + 2 * n1 + (m0 & 1)] = c[nt][1];
        xf[(m1 >> 1) * 64 + 2 * n0 + (m1 & 1)] = c[nt][2];
        xf[(m1 >> 1) * 64 + 2 * n1 + (m1 & 1)] = c[nt][3];
    }
}

// ---------------- K3a (FFMA): t = sum_i Xf * w{1|2} ----------------
__global__ void __launch_bounds__(256) k3a_mixx(const float* __restrict__ wx1,
                                                const float* __restrict__ wx2) {
    __shared__ float2 sX[CINN][M2N];
    __shared__ float2 sW[CINN][COUTT];
    const int tid = threadIdx.x;
    const int kxi = blockIdx.x, b = blockIdx.y;
    const int m = (kxi < 32) ? kxi : (kxi - 32);
    const float2* wsrc = (const float2*)((kxi < 32) ? wx1 : wx2);

    for (int idx = tid; idx < CINN * M2N; idx += 256) {
        int i = idx >> 5, k = idx & 31;
        sX[i][k] = g_Xf[((b * CINN + i) * KXN + kxi) * M2N + k];
    }
    for (int idx = tid; idx < CINN * COUTT; idx += 256) {
        int i = idx >> 6, c = idx & 63;
        sW[i][c] = wsrc[(i * COUTT + c) * M1N + m];
    }
    __syncthreads();

    const int ky = tid & 31;
    const int cb = (tid >> 5) << 3;
    float2 acc[8];
#pragma unroll
    for (int j = 0; j < 8; j++) acc[j] = make_float2(0.f, 0.f);
    for (int i = 0; i < CINN; i++) {
        float2 xv = sX[i][ky];
#pragma unroll
        for (int j = 0; j < 8; j++) {
            float2 wv = sW[i][cb + j];
            acc[j].x = fmaf(xv.x, wv.x, fmaf(-xv.y, wv.y, acc[j].x));
            acc[j].y = fmaf(xv.x, wv.y, fmaf( xv.y, wv.x, acc[j].y));
        }
    }
#pragma unroll
    for (int j = 0; j < 8; j++)
        g_T[((b * COUTT + cb + j) * KXN + kxi) * M2N + ky] = acc[j];
}

// ---------------- K3b (FFMA): OutF = sum_c t * wy ----------------
__global__ void __launch_bounds__(256) k3b_mixy(const float* __restrict__ wy) {
    __shared__ float2 sT[32][KXN];
    __shared__ float2 sWy[32][COUTT];
    const int tid = threadIdx.x;
    const int ky = blockIdx.x, b = blockIdx.y;
    const int kxi = tid & 63;
    const int ob = (tid >> 6) << 4;
    const float2* wyp = (const float2*)wy;

    float2 acc[16];
#pragma unroll
    for (int j = 0; j < 16; j++) acc[j] = make_float2(0.f, 0.f);

    for (int cb = 0; cb < COUTT; cb += 32) {
        __syncthreads();
        for (int idx = tid; idx < 32 * KXN; idx += 256) {
            int cl = idx >> 6, kk = idx & 63;
            sT[cl][kk] = g_T[((b * COUTT + cb + cl) * KXN + kk) * M2N + ky];
        }
        for (int idx = tid; idx < 32 * COUTT; idx += 256) {
            int cl = idx >> 6, o = idx & 63;
            sWy[cl][o] = wyp[((cb + cl) * COUTT + o) * M2N + ky];
        }
        __syncthreads();
        for (int cl = 0; cl < 32; cl++) {
            float2 tv = sT[cl][kxi];
#pragma unroll
            for (int j = 0; j < 16; j++) {
                float2 wv = sWy[cl][ob + j];
                acc[j].x = fmaf(tv.x, wv.x, fmaf(-tv.y, wv.y, acc[j].x));
                acc[j].y = fmaf(tv.x, wv.y, fmaf( tv.y, wv.x, acc[j].y));
            }
        }
    }
#pragma unroll
    for (int j = 0; j < 16; j++)
        g_OutF[((b * COUTT + ob + j) * KXN + kxi) * M2N + ky] = acc[j];
}

// ---------------- S5: Z = A5 @ OutFslab  (per (b,o): M=512, K=128, N=32) ----------------
__global__ void __launch_bounds__(256) s5_invh() {
    __shared__ float sA[256][17];
    __shared__ float sF[64][66];
    const int tid = threadIdx.x, warp = tid >> 5, lane = tid & 31;
    const int g = lane >> 2, tg = lane & 3;
    const int mh = blockIdx.x, bo = blockIdx.y;

    const float* outf = (const float*)g_OutF + (size_t)bo * 4096;
    for (int i = tid; i < 64 * 64; i += 256) {
        int r = i >> 6, cc = i & 63;
        sF[r][cc] = outf[r * 64 + cc];
    }

    float c[2][4][4];
#pragma unroll
    for (int a = 0; a < 2; a++)
#pragma unroll
        for (int i = 0; i < 4; i++)
#pragma unroll
            for (int j = 0; j < 4; j++) c[a][i][j] = 0.f;

    for (int kc = 0; kc < 8; kc++) {
        __syncthreads();
        for (int i = tid; i < 256 * 16; i += 256) {
            int row = i >> 4, col = i & 15;
            sA[row][col] = g_A5[(mh * 256 + row) * 128 + kc * 16 + col];
        }
        __syncthreads();
#pragma unroll
        for (int ks = 0; ks < 2; ks++) {
            int kg0 = kc * 16 + ks * 8 + tg, kg1 = kg0 + 4;
            unsigned bharr[4][2], blarr[4][2];
#pragma unroll
            for (int nt = 0; nt < 4; nt++) {
                int n = nt * 8 + g;
                split2(sF[kg0 >> 1][2 * n + (kg0 & 1)], bharr[nt][0], blarr[nt][0]);
                split2(sF[kg1 >> 1][2 * n + (kg1 & 1)], bharr[nt][1], blarr[nt][1]);
            }
#pragma unroll
            for (int mt = 0; mt < 2; mt++) {
                int r = warp * 32 + mt * 16;
                unsigned ah[4], al[4];
                split2(sA[r + g    ][ks * 8 + tg    ], ah[0], al[0]);
                split2(sA[r + g + 8][ks * 8 + tg    ], ah[1], al[1]);
                split2(sA[r + g    ][ks * 8 + tg + 4], ah[2], al[2]);
                split2(sA[r + g + 8][ks * 8 + tg + 4], ah[3], al[3]);
#pragma unroll
                for (int nt = 0; nt < 4; nt++)
                    mma3(c[mt][nt], ah, al, bharr[nt], blarr[nt]);
            }
        }
    }
    float* z = g_Z + (size_t)bo * 16384;
#pragma unroll
    for (int mt = 0; mt < 2; mt++)
#pragma unroll
        for (int nt = 0; nt < 4; nt++) {
            int m0 = mh * 256 + warp * 32 + mt * 16 + g, m1 = m0 + 8;
            int n0 = nt * 8 + 2 * tg, n1 = n0 + 1;
            z[(m0 >> 1) * 64 + 2 * n0 + (m0 & 1)] = c[mt][nt][0];
            z[(m0 >> 1) * 64 + 2 * n1 + (m0 & 1)] = c[mt][nt][1];
            z[(m1 >> 1) * 64 + 2 * n0 + (m1 & 1)] = c[mt][nt][2];
            z[(m1 >> 1) * 64 + 2 * n1 + (m1 & 1)] = c[mt][nt][3];
        }
}

// ---------------- S6: out = Zslab @ C6  (per (b,o): M=256, K=64, N=256) ----------------
__global__ void __launch_bounds__(256) s6_invw(float* __restrict__ out) {
    __shared__ float sZ[128][33];
    __shared__ float sC[32][129];
    const int tid = threadIdx.x, warp = tid >> 5, lane = tid & 31;
    const int g = lane >> 2, tg = lane & 3;
    const int mt2 = blockIdx.x, nt2 = blockIdx.y, bo = blockIdx.z;

    float c[16][4];
#pragma unroll
    for (int i = 0; i < 16; i++)
#pragma unroll
        for (int j = 0; j < 4; j++) c[i][j] = 0.f;

    const float* z = g_Z + (size_t)bo * 16384;
    for (int kc = 0; kc < 2; kc++) {
        __syncthreads();
        for (int i = tid; i < 128 * 32; i += 256) {
            int row = i >> 5, col = i & 31;
            sZ[row][col] = z[(mt2 * 128 + row) * 64 + kc * 32 + col];
        }
        for (int i = tid; i < 32 * 128; i += 256) {
            int k = i >> 7, n = i & 127;
            sC[k][n] = g_C6[(kc * 32 + k) * 256 + nt2 * 128 + n];
        }
        __syncthreads();
#pragma unroll
        for (int ks = 0; ks < 4; ks++) {
            unsigned ah[4], al[4];
            split2(sZ[warp * 16 + g    ][ks * 8 + tg    ], ah[0], al[0]);
            split2(sZ[warp * 16 + g + 8][ks * 8 + tg    ], ah[1], al[1]);
            split2(sZ[warp * 16 + g    ][ks * 8 + tg + 4], ah[2], al[2]);
            split2(sZ[warp * 16 + g + 8][ks * 8 + tg + 4], ah[3], al[3]);
#pragma unroll
            for (int nt = 0; nt < 16; nt++) {
                unsigned bh[2], bl[2];
                split2(sC[ks * 8 + tg    ][nt * 8 + g], bh[0], bl[0]);
                split2(sC[ks * 8 + tg + 4][nt * 8 + g], bh[1], bl[1]);
                mma3(c[nt], ah, al, bh, bl);
            }
        }
    }
    float* orow = out + (size_t)bo * 65536;
#pragma unroll
    for (int nt = 0; nt < 16; nt++) {
        int h = mt2 * 128 + warp * 16 + g;
        int w = nt2 * 128 + nt * 8 + 2 * tg;
        *(float2*)&orow[(h)     * 256 + w] = make_float2(c[nt][0], c[nt][1]);
        *(float2*)&orow[(h + 8) * 256 + w] = make_float2(c[nt][2], c[nt][3]);
    }
}

extern "C" void kernel_launch(void* const* d_in, const int* in_sizes, int n_in,
                              void* d_out, int out_size) {
    const float* x   = (const float*)d_in[0];
    const float* wx1 = (const float*)d_in[1];
    const float* wx2 = (const float*)d_in[2];
    const float* wy  = (const float*)d_in[3];
    float* out = (float*)d_out;

    fill_B1<<<64, 256>>>();
    fill_A2<<<256, 256>>>();
    fill_A5<<<256, 256>>>();
    fill_C6<<<64, 256>>>();

    s1_wdft<<<2048, 256>>>(x);                 // W-DFT
    s2_hdft<<<1024, 256>>>();                  // H-DFT
    k3a_mixx<<<dim3(KXN, BB), 256>>>(wx1, wx2);
    k3b_mixy<<<dim3(M2N, BB), 256>>>(wy);
    s5_invh<<<dim3(2, 1024), 256>>>();         // inverse H
    s6_invw<<<dim3(2, 2, 1024), 256>>>(out);   // inverse W (irfft)
}